// round 4
// baseline (speedup 1.0000x reference)
#include <cuda_runtime.h>

// Problem constants (fixed by reference setup_inputs)
#define BQ 32
#define NQ 300
#define CQ 92
#define TQ 50
#define ROWS_TOTAL (BQ * NQ)   // 9600 pred rows
#define COLS (BQ * TQ)         // 1600 target cols
#define QUADS (COLS / 4)       // 400 float4 column groups
#define ROWS_PER_BLOCK 8
#define THREADS 416            // 13 warps: warps 0..7 do softmax rows, threads 0..399 own quads

// Cost coefficients
#define W_CLASS 1.0f
#define W_BBOX  5.0f
#define W_GIOU  2.0f

__global__ __launch_bounds__(THREADS, 1)
void matcher_cost_kernel(const float* __restrict__ logits,  // (9600, 92)
                         const float* __restrict__ pboxes,  // (9600, 4) cxcywh
                         const int*   __restrict__ tlabels, // (1600,) int32
                         const float* __restrict__ tboxes,  // (1600, 4) cxcywh
                         float* __restrict__ out)           // (9600, 1600)
{
    __shared__ float probs[ROWS_PER_BLOCK][CQ];

    const int tid  = threadIdx.x;
    const int wid  = tid >> 5;
    const int lane = tid & 31;
    const int row0 = blockIdx.x * ROWS_PER_BLOCK;

    // ---- Softmax prologue: warp r computes softmax of pred row (row0 + r) ----
    if (wid < ROWS_PER_BLOCK) {
        const float* lg = logits + (size_t)(row0 + wid) * CQ;
        float x0 = lg[lane];
        float x1 = lg[32 + lane];
        float x2 = (lane < CQ - 64) ? lg[64 + lane] : -1e30f;
        float m = fmaxf(fmaxf(x0, x1), x2);
        #pragma unroll
        for (int o = 16; o; o >>= 1) m = fmaxf(m, __shfl_xor_sync(0xFFFFFFFFu, m, o));
        float e0 = __expf(x0 - m);
        float e1 = __expf(x1 - m);
        float e2 = (lane < CQ - 64) ? __expf(x2 - m) : 0.0f;
        float s = e0 + e1 + e2;
        #pragma unroll
        for (int o = 16; o; o >>= 1) s += __shfl_xor_sync(0xFFFFFFFFu, s, o);
        float rs = __fdividef(1.0f, s);
        probs[wid][lane]      = e0 * rs;
        probs[wid][32 + lane] = e1 * rs;
        if (lane < CQ - 64) probs[wid][64 + lane] = e2 * rs;
    }

    // ---- Load this thread's 4 target columns into registers (row-invariant) ----
    float tx0[4], ty0[4], tx1[4], ty1[4];
    float tcx[4], tcy[4], ttw[4], tth[4], tar[4];
    int   cid[4];
    const bool active = (tid < QUADS);
    if (active) {
        const int c0 = tid * 4;
        #pragma unroll
        for (int j = 0; j < 4; j++) {
            float4 bb = reinterpret_cast<const float4*>(tboxes)[c0 + j];
            float w = bb.z, h = bb.w;
            tcx[j] = bb.x; tcy[j] = bb.y; ttw[j] = w; tth[j] = h;
            tx0[j] = bb.x - 0.5f * w; tx1[j] = bb.x + 0.5f * w;
            ty0[j] = bb.y - 0.5f * h; ty1[j] = bb.y + 0.5f * h;
            tar[j] = w * h;
            // int32 labels (JAX default x64-disabled). Clamp defensively so a
            // surprise layout yields wrong values (rel_err catch), not a trap.
            int c = tlabels[c0 + j];
            cid[j] = min(max(c, 0), CQ - 1);
        }
    }

    __syncthreads();

    if (!active) return;

    // ---- Row loop: 8 pred rows against this thread's 4 columns ----
    #pragma unroll 2
    for (int r = 0; r < ROWS_PER_BLOCK; r++) {
        const int row = row0 + r;
        float4 pb = reinterpret_cast<const float4*>(pboxes)[row];   // broadcast load, L1 hit
        const float pw = pb.z, ph = pb.w;
        const float px0 = pb.x - 0.5f * pw, px1 = pb.x + 0.5f * pw;
        const float py0 = pb.y - 0.5f * ph, py1 = pb.y + 0.5f * ph;
        const float par = pw * ph;

        float o4[4];
        #pragma unroll
        for (int j = 0; j < 4; j++) {
            // intersection
            float ltx = fmaxf(px0, tx0[j]);
            float lty = fmaxf(py0, ty0[j]);
            float rbx = fminf(px1, tx1[j]);
            float rby = fminf(py1, ty1[j]);
            float wx = fmaxf(rbx - ltx, 0.0f);
            float wy = fmaxf(rby - lty, 0.0f);
            float inter = wx * wy;
            float uni = par + tar[j] - inter;
            // enclosing box
            float ex = fmaxf(px1, tx1[j]) - fminf(px0, tx0[j]);
            float ey = fmaxf(py1, ty1[j]) - fminf(py0, ty0[j]);
            float ear = ex * ey;
            // 2*cost_giou = 2 - 2*(inter*ear + uni*uni) / (uni*ear)  -- single rcp
            float num  = fmaf(uni, uni, inter * ear);
            float frac = __fdividef(num, uni * ear);
            // L1 in cxcywh space
            float d0 = pb.x - tcx[j];
            float d1 = pw   - ttw[j];
            float d2 = pb.y - tcy[j];
            float d3 = ph   - tth[j];
            float s1 = fabsf(d0) + fabsf(d2);
            float s2 = fabsf(d1) + fabsf(d3);
            float l1 = s1 + s2;
            // class cost: -prob[row][cid]
            float pr = probs[r][cid[j]];
            // cost = 5*l1 - pr + 2 - 2*frac
            o4[j] = fmaf(W_BBOX, l1, fmaf(-W_GIOU, frac, (W_GIOU - W_CLASS * pr)));
        }
        float4 res = make_float4(o4[0], o4[1], o4[2], o4[3]);
        reinterpret_cast<float4*>(out + (size_t)row * COLS)[tid] = res;
    }
}

extern "C" void kernel_launch(void* const* d_in, const int* in_sizes, int n_in,
                              void* d_out, int out_size)
{
    const float* logits  = (const float*)d_in[0];  // (32,300,92)
    const float* pboxes  = (const float*)d_in[1];  // (32,300,4)
    const int*   tlabels = (const int*)d_in[2];    // (32,50) int32
    const float* tboxes  = (const float*)d_in[3];  // (32,50,4)
    float*       out     = (float*)d_out;          // (32,300,1600)

    (void)in_sizes; (void)n_in; (void)out_size;

    dim3 grid(ROWS_TOTAL / ROWS_PER_BLOCK);  // 1200
    dim3 block(THREADS);                      // 416
    matcher_cost_kernel<<<grid, block>>>(logits, pboxes, tlabels, tboxes, out);
}

// round 5
// speedup vs baseline: 1.1497x; 1.1497x over previous
#include <cuda_runtime.h>

// Problem constants (fixed by reference setup_inputs)
#define BQ 32
#define NQ 300
#define CQ 92
#define TQ 50
#define ROWS_TOTAL (BQ * NQ)   // 9600 pred rows
#define COLS (BQ * TQ)         // 1600 target cols
#define QUADS (COLS / 4)       // 400 float4 column groups
#define ROWS_PER_BLOCK 8
#define THREADS 416            // 13 warps: warps 0..7 do softmax rows, threads 0..399 own quads

// Cost coefficients
#define W_CLASS 1.0f
#define W_BBOX  5.0f
#define W_GIOU  2.0f

__global__ __launch_bounds__(THREADS, 2)   // force <=78 regs -> 2 CTAs/SM, 26 warps
void matcher_cost_kernel(const float* __restrict__ logits,  // (9600, 92)
                         const float* __restrict__ pboxes,  // (9600, 4) cxcywh
                         const int*   __restrict__ tlabels, // (1600,) int32
                         const float* __restrict__ tboxes,  // (1600, 4) cxcywh
                         float* __restrict__ out)           // (9600, 1600)
{
    __shared__ float probs[ROWS_PER_BLOCK][CQ];

    const int tid  = threadIdx.x;
    const int wid  = tid >> 5;
    const int lane = tid & 31;
    const int row0 = blockIdx.x * ROWS_PER_BLOCK;

    // ---- Softmax prologue: warp r computes softmax of pred row (row0 + r) ----
    if (wid < ROWS_PER_BLOCK) {
        const float* lg = logits + (size_t)(row0 + wid) * CQ;
        float x0 = lg[lane];
        float x1 = lg[32 + lane];
        float x2 = (lane < CQ - 64) ? lg[64 + lane] : -1e30f;
        float m = fmaxf(fmaxf(x0, x1), x2);
        #pragma unroll
        for (int o = 16; o; o >>= 1) m = fmaxf(m, __shfl_xor_sync(0xFFFFFFFFu, m, o));
        float e0 = __expf(x0 - m);
        float e1 = __expf(x1 - m);
        float e2 = (lane < CQ - 64) ? __expf(x2 - m) : 0.0f;
        float s = e0 + e1 + e2;
        #pragma unroll
        for (int o = 16; o; o >>= 1) s += __shfl_xor_sync(0xFFFFFFFFu, s, o);
        float rs = __fdividef(1.0f, s);
        probs[wid][lane]      = e0 * rs;
        probs[wid][32 + lane] = e1 * rs;
        if (lane < CQ - 64) probs[wid][64 + lane] = e2 * rs;
    }

    // ---- Column cache: xyxy corners + area + class only (6 regs/col) ----
    float tx0[4], ty0[4], tx1[4], ty1[4], tar[4];
    int   cid[4];
    const bool active = (tid < QUADS);
    if (active) {
        const int c0 = tid * 4;
        #pragma unroll
        for (int j = 0; j < 4; j++) {
            float4 bb = reinterpret_cast<const float4*>(tboxes)[c0 + j];
            float w = bb.z, h = bb.w;
            tx0[j] = bb.x - 0.5f * w; tx1[j] = bb.x + 0.5f * w;
            ty0[j] = bb.y - 0.5f * h; ty1[j] = bb.y + 0.5f * h;
            tar[j] = w * h;
            int c = tlabels[c0 + j];            // int32 labels
            cid[j] = min(max(c, 0), CQ - 1);    // defensive clamp (prologue only)
        }
    }

    __syncthreads();

    if (!active) return;

    // ---- Row loop: 8 pred rows against this thread's 4 columns ----
    #pragma unroll 1
    for (int r = 0; r < ROWS_PER_BLOCK; r++) {
        const int row = row0 + r;
        float4 pb = reinterpret_cast<const float4*>(pboxes)[row];   // broadcast, L1 hit
        const float pw = pb.z, ph = pb.w;
        const float px0 = pb.x - 0.5f * pw, px1 = pb.x + 0.5f * pw;
        const float py0 = pb.y - 0.5f * ph, py1 = pb.y + 0.5f * ph;
        const float par = pw * ph;

        float o4[4];
        #pragma unroll
        for (int j = 0; j < 4; j++) {
            // intersection
            float ltx = fmaxf(px0, tx0[j]);
            float lty = fmaxf(py0, ty0[j]);
            float rbx = fminf(px1, tx1[j]);
            float rby = fminf(py1, ty1[j]);
            float wx = fmaxf(rbx - ltx, 0.0f);
            float wy = fmaxf(rby - lty, 0.0f);
            float inter = wx * wy;
            float uni = par + tar[j] - inter;
            // enclosing box
            float ex = fmaxf(px1, tx1[j]) - fminf(px0, tx0[j]);
            float ey = fmaxf(py1, ty1[j]) - fminf(py0, ty0[j]);
            float ear = ex * ey;
            // 2*cost_giou = 2 - 2*(inter*ear + uni*uni) / (uni*ear)  -- single rcp
            float num  = fmaf(uni, uni, inter * ear);
            float frac = __fdividef(num, uni * ear);
            // L1 in cxcywh derived from xyxy deltas:
            //   d0+d1 = 2*dcx, d1-d0 = dw  (same for y)
            float d0 = px0 - tx0[j];
            float d1 = px1 - tx1[j];
            float e0y = py0 - ty0[j];
            float e1y = py1 - ty1[j];
            float cxs = d0 + d1;     // 2*dcx
            float cys = e0y + e1y;   // 2*dcy
            float dws = d1 - d0;     // dw
            float dhs = e1y - e0y;   // dh
            float sA = fabsf(cxs) + fabsf(cys);   // 2*(|dcx|+|dcy|)
            float sB = fabsf(dws) + fabsf(dhs);   // |dw|+|dh|
            // class cost: -prob[row][cid]
            float pr = probs[r][cid[j]];
            // cost = 5*(0.5*sA + sB) - pr + 2 - 2*frac
            float base = fmaf(-W_GIOU, frac, (W_GIOU - W_CLASS * pr));
            o4[j] = fmaf(0.5f * W_BBOX, sA, fmaf(W_BBOX, sB, base));
        }
        float4 res = make_float4(o4[0], o4[1], o4[2], o4[3]);
        reinterpret_cast<float4*>(out + (size_t)row * COLS)[tid] = res;
    }
}

extern "C" void kernel_launch(void* const* d_in, const int* in_sizes, int n_in,
                              void* d_out, int out_size)
{
    const float* logits  = (const float*)d_in[0];  // (32,300,92)
    const float* pboxes  = (const float*)d_in[1];  // (32,300,4)
    const int*   tlabels = (const int*)d_in[2];    // (32,50) int32
    const float* tboxes  = (const float*)d_in[3];  // (32,50,4)
    float*       out     = (float*)d_out;          // (32,300,1600)

    (void)in_sizes; (void)n_in; (void)out_size;

    dim3 grid(ROWS_TOTAL / ROWS_PER_BLOCK);  // 1200
    dim3 block(THREADS);                      // 416
    matcher_cost_kernel<<<grid, block>>>(logits, pboxes, tlabels, tboxes, out);
}

// round 6
// speedup vs baseline: 1.1662x; 1.0144x over previous
#include <cuda_runtime.h>

// Problem constants (fixed by reference setup_inputs)
#define BQ 32
#define NQ 300
#define CQ 92
#define TQ 50
#define ROWS_TOTAL (BQ * NQ)   // 9600 pred rows
#define COLS (BQ * TQ)         // 1600 target cols
#define ROWS_PER_BLOCK 8
#define THREADS 800            // 25 warps; warps 0..7 do softmax; every thread owns 2 cols

__global__ __launch_bounds__(THREADS, 2)   // cap 40 regs -> 2 CTAs/SM = 50 warps (78% occ)
void matcher_cost_kernel(const float* __restrict__ logits,  // (9600, 92)
                         const float* __restrict__ pboxes,  // (9600, 4) cxcywh
                         const int*   __restrict__ tlabels, // (1600,) int32
                         const float* __restrict__ tboxes,  // (1600, 4) cxcywh
                         float* __restrict__ out)           // (9600, 1600)
{
    __shared__ float probs[ROWS_PER_BLOCK][CQ];

    const int tid  = threadIdx.x;
    const int wid  = tid >> 5;
    const int lane = tid & 31;
    const int row0 = blockIdx.x * ROWS_PER_BLOCK;

    // ---- Softmax prologue: warp r computes softmax of pred row (row0 + r) ----
    if (wid < ROWS_PER_BLOCK) {
        const float* lg = logits + (size_t)(row0 + wid) * CQ;
        float x0 = lg[lane];
        float x1 = lg[32 + lane];
        float x2 = (lane < CQ - 64) ? lg[64 + lane] : -1e30f;
        float m = fmaxf(fmaxf(x0, x1), x2);
        #pragma unroll
        for (int o = 16; o; o >>= 1) m = fmaxf(m, __shfl_xor_sync(0xFFFFFFFFu, m, o));
        float e0 = __expf(x0 - m);
        float e1 = __expf(x1 - m);
        float e2 = (lane < CQ - 64) ? __expf(x2 - m) : 0.0f;
        float s = e0 + e1 + e2;
        #pragma unroll
        for (int o = 16; o; o >>= 1) s += __shfl_xor_sync(0xFFFFFFFFu, s, o);
        float rs = __fdividef(1.0f, s);
        probs[wid][lane]      = e0 * rs;
        probs[wid][32 + lane] = e1 * rs;
        if (lane < CQ - 64) probs[wid][64 + lane] = e2 * rs;
    }

    // ---- Column cache: 2 cols/thread (xyxy corners + w/h + area + class) ----
    float tx0[2], ty0[2], tx1[2], ty1[2], ttw[2], tth[2], tar[2];
    int   cid[2];
    {
        const int c0 = tid * 2;
        #pragma unroll
        for (int j = 0; j < 2; j++) {
            float4 bb = reinterpret_cast<const float4*>(tboxes)[c0 + j];
            float w = bb.z, h = bb.w;
            ttw[j] = w; tth[j] = h;
            tx0[j] = bb.x - 0.5f * w; tx1[j] = bb.x + 0.5f * w;
            ty0[j] = bb.y - 0.5f * h; ty1[j] = bb.y + 0.5f * h;
            tar[j] = w * h;
            int c = tlabels[c0 + j];            // int32 labels
            cid[j] = min(max(c, 0), CQ - 1);    // defensive clamp (prologue only)
        }
    }

    __syncthreads();

    // ---- Row loop: 8 pred rows against this thread's 2 columns ----
    #pragma unroll 1
    for (int r = 0; r < ROWS_PER_BLOCK; r++) {
        const int row = row0 + r;
        float4 pb = reinterpret_cast<const float4*>(pboxes)[row];   // broadcast, L1 hit
        const float pw = pb.z, ph = pb.w;
        const float px0 = pb.x - 0.5f * pw, px1 = pb.x + 0.5f * pw;
        const float py0 = pb.y - 0.5f * ph, py1 = pb.y + 0.5f * ph;
        const float par = pw * ph;

        float o2[2];
        #pragma unroll
        for (int j = 0; j < 2; j++) {
            // intersection (4 FMNMX)
            float ltx = fmaxf(px0, tx0[j]);
            float lty = fmaxf(py0, ty0[j]);
            float rbx = fminf(px1, tx1[j]);
            float rby = fminf(py1, ty1[j]);
            float gx = rbx - ltx;
            float gy = rby - lty;
            float wx = fmaxf(gx, 0.0f);
            float wy = fmaxf(gy, 0.0f);
            float inter = wx * wy;
            // enclosing box via identity: enclose_w = pw + tw - (rbx - ltx)
            float ex = (pw + ttw[j]) - gx;
            float ey = (ph + tth[j]) - gy;
            float ear = ex * ey;
            float uni = (par + tar[j]) - inter;
            // 2*cost_giou = 2 - 2*(inter*ear + uni*uni)/(uni*ear)  -- single rcp
            float num  = fmaf(uni, uni, inter * ear);
            float frac = __fdividef(num, uni * ear);
            // L1 in cxcywh: 2*dcx = (px0-tx0)+(px1-tx1); dw = pw - tw
            float dcx2 = (px0 - tx0[j]) + (px1 - tx1[j]);
            float dcy2 = (py0 - ty0[j]) + (py1 - ty1[j]);
            float dw = pw - ttw[j];
            float dh = ph - tth[j];
            float sA = fabsf(dcx2) + fabsf(dcy2);   // 2*(|dcx|+|dcy|)
            float sB = fabsf(dw) + fabsf(dh);       // |dw|+|dh|
            // class cost: -prob[row][cid]
            float pr = probs[r][cid[j]];
            // cost = 2.5*sA + 5*sB + (2 - pr - 2*frac)
            float base = fmaf(-2.0f, frac, 2.0f - pr);
            o2[j] = fmaf(2.5f, sA, fmaf(5.0f, sB, base));
        }
        float2 res = make_float2(o2[0], o2[1]);
        reinterpret_cast<float2*>(out + (size_t)row * COLS)[tid] = res;
    }
}

extern "C" void kernel_launch(void* const* d_in, const int* in_sizes, int n_in,
                              void* d_out, int out_size)
{
    const float* logits  = (const float*)d_in[0];  // (32,300,92)
    const float* pboxes  = (const float*)d_in[1];  // (32,300,4)
    const int*   tlabels = (const int*)d_in[2];    // (32,50) int32
    const float* tboxes  = (const float*)d_in[3];  // (32,50,4)
    float*       out     = (float*)d_out;          // (32,300,1600)

    (void)in_sizes; (void)n_in; (void)out_size;

    dim3 grid(ROWS_TOTAL / ROWS_PER_BLOCK);  // 1200
    dim3 block(THREADS);                      // 800
    matcher_cost_kernel<<<grid, block>>>(logits, pboxes, tlabels, tboxes, out);
}